// round 1
// baseline (speedup 1.0000x reference)
#include <cuda_runtime.h>
#include <math.h>
#include <stdint.h>

#define BNS 0.9995003746f  // float32(1/sqrt(1+1e-3))

#define B  8
#define NP 2048
#define KNN 64
#define TU 256
#define FEAT 576   // 3*K*3
#define M_TOT (B*NP)   // 16384

// ---------------- scratch (device globals; no allocation allowed) ----------------
__device__ float g_xmax[B*TU];
__device__ float g_T[B*9];
__device__ float g_pts[B*NP*3];
__device__ float g_feats[M_TOT*FEAT];     // 37.7 MB
__device__ float g_f0[M_TOT*512];         // 33.5 MB
__device__ float g_f1[M_TOT*512];         // 33.5 MB

// ---------------- T-Net stage 1: 1x1 conv + BN + ReLU + global max over N ----------------
__global__ void tnet_conv_max(const float* __restrict__ points,
                              const float* __restrict__ tw, const float* __restrict__ tb,
                              const float* __restrict__ tg1, const float* __restrict__ tbt1,
                              float* __restrict__ xmax)
{
    __shared__ float P[NP*3];
    int b = blockIdx.x, u = threadIdx.x;
    const float* pb = points + b*NP*3;
    for (int t = u; t < NP*3; t += TU) P[t] = pb[t];
    __syncthreads();
    float w0 = tw[u], w1 = tw[TU+u], w2 = tw[2*TU+u], bb = tb[u];
    float al = tg1[u]*BNS, bt = tbt1[u];
    float m = 0.f;
    for (int n = 0; n < NP; n++) {
        float z = P[n*3]*w0 + P[n*3+1]*w1 + P[n*3+2]*w2 + bb;
        z = fmaxf(z*al + bt, 0.f);
        m = fmaxf(m, z);
    }
    xmax[b*TU+u] = m;
}

// ---------------- T-Net stage 2: dense->BN->ReLU, then 9-wide dense -> T matrix ----------------
__global__ void tnet_dense(const float* __restrict__ xmax,
                           const float* __restrict__ td1w, const float* __restrict__ td1b,
                           const float* __restrict__ tg2, const float* __restrict__ tbt2,
                           const float* __restrict__ td2w, const float* __restrict__ td2b,
                           float* __restrict__ Tout)
{
    __shared__ float xm[TU];
    __shared__ float x2[TU];
    int b = blockIdx.x, u = threadIdx.x;
    xm[u] = xmax[b*TU+u];
    __syncthreads();
    float s = td1b[u];
    for (int v = 0; v < TU; v++) s += xm[v]*td1w[v*TU+u];
    s = fmaxf(s*(tg2[u]*BNS) + tbt2[u], 0.f);
    x2[u] = s;
    __syncthreads();
    if (u < 9) {
        float t = td2b[u];
        for (int v = 0; v < TU; v++) t += x2[v]*td2w[v*9+u];
        Tout[b*9+u] = t;
    }
}

// ---------------- apply T: pts = points @ T ----------------
__global__ void transform_pts(const float* __restrict__ points,
                              const float* __restrict__ Tm, float* __restrict__ pts)
{
    int i = blockIdx.x*256 + threadIdx.x;
    if (i >= M_TOT) return;
    int b = i >> 11;
    const float* T = Tm + b*9;
    float x = points[i*3], y = points[i*3+1], z = points[i*3+2];
    pts[i*3+0] = x*T[0] + y*T[3] + z*T[6];
    pts[i*3+1] = x*T[1] + y*T[4] + z*T[7];
    pts[i*3+2] = x*T[2] + y*T[5] + z*T[8];
}

// ---------------- ball query + stable top-K + gather -> feats ----------------
// one block (256 threads) per (b,i); exact argsort(-score) semantics:
//  - candidates with score>0 sorted descending by score, ties -> ascending index
//  - remaining slots filled with score==0 indices in ascending order
__global__ void ballquery_kernel(const float* __restrict__ noise, float* __restrict__ feats)
{
    extern __shared__ char smraw[];
    float* ptsS = (float*)smraw;                        // 6144 floats
    float* noiS = ptsS + NP*3;                          // 2048
    float* dS   = noiS + NP;                            // 2048
    unsigned long long* buf = (unsigned long long*)(dS + NP); // 2048 u64
    int* idxS = (int*)(buf + NP);                       // 64
    __shared__ int cnt;

    int b = blockIdx.x >> 11;
    int i = blockIdx.x & (NP-1);
    int tid = threadIdx.x;

    const float* pg = g_pts + b*NP*3;
    for (int t = tid; t < NP*3; t += 256) ptsS[t] = pg[t];
    const float* ng = noise + ((size_t)b*NP + i)*NP;
    for (int t = tid; t < NP; t += 256) noiS[t] = ng[t];
    __syncthreads();

    float px = ptsS[i*3], py = ptsS[i*3+1], pz = ptsS[i*3+2];
    for (int j = tid; j < NP; j += 256) {
        float dx = px - ptsS[j*3], dy = py - ptsS[j*3+1], dz = pz - ptsS[j*3+2];
        dS[j] = sqrtf(dx*dx + dy*dy + dz*dz);
    }
    __syncthreads();

    const float radii[3] = {0.1f, 0.3f, 0.7f};
    float* fout = feats + ((size_t)blockIdx.x)*FEAT;

    for (int r = 0; r < 3; r++) {
        float rad = radii[r];
        if (tid == 0) cnt = 0;
        __syncthreads();
        for (int j = tid; j < NP; j += 256) {
            float sc = noiS[j];
            if (dS[j] <= rad && sc > 0.f) {
                int p = atomicAdd(&cnt, 1);
                buf[p] = ((unsigned long long)__float_as_uint(sc) << 32)
                       | (unsigned)(0xFFFFFFFFu - (unsigned)j);
            }
        }
        __syncthreads();
        int c = cnt;
        int S = 64; while (S < c) S <<= 1;
        for (int t = c + tid; t < S; t += 256) buf[t] = 0ULL;
        __syncthreads();
        // bitonic sort, descending (keys unique -> deterministic result)
        for (int k = 2; k <= S; k <<= 1) {
            for (int jj = k >> 1; jj > 0; jj >>= 1) {
                for (int t = tid; t < S; t += 256) {
                    int ixj = t ^ jj;
                    if (ixj > t) {
                        bool desc = ((t & k) == 0);
                        unsigned long long x = buf[t], y = buf[ixj];
                        if ((x < y) == desc) { buf[t] = y; buf[ixj] = x; }
                    }
                }
                __syncthreads();
            }
        }
        int cc = c < KNN ? c : KNN;
        if (tid < KNN && tid < cc)
            idxS[tid] = (int)(0xFFFFFFFFu - (unsigned)(buf[tid] & 0xFFFFFFFFu));
        __syncthreads();
        if (tid == 0 && c < KNN) {
            int w = c;
            for (int j = 0; j < NP && w < KNN; j++)
                if (!(dS[j] <= rad && noiS[j] > 0.f)) idxS[w++] = j;
        }
        __syncthreads();
        // feats[b,i, k*9 + r*3 + coord] = pts[b, idx[k], coord]
        for (int t = tid; t < KNN*3; t += 256) {
            int k = t / 3, co = t % 3;
            fout[k*9 + r*3 + co] = ptsS[idxS[k]*3 + co];
        }
        __syncthreads();
    }
}

// ---------------- fused SGEMM: C = epilogue(A[M,K] @ W[K,N]) ----------------
// MODE 0: relu(bn(acc + bias, gamma, beta))          -> out[m*N+n]
// MODE 1: resIn[m*N+n] + acc + bias[n]               -> out[m*N+n]
// MODE 2: relu(bn(...)) then atomicMax into out[(m>>11)*N + n]  (max over points)
template<int MODE>
__global__ void gemm_fused(const float* __restrict__ A, const float* __restrict__ W,
                           const float* __restrict__ bias, const float* __restrict__ gamma,
                           const float* __restrict__ beta, const float* __restrict__ resIn,
                           float* __restrict__ out, int M, int K, int N)
{
    __shared__ float As[8][128];
    __shared__ float Bs[8][128];
    int tid = threadIdx.x;
    int row0 = blockIdx.y * 128, col0 = blockIdx.x * 128;
    int tx = tid & 15, ty = tid >> 4;
    float acc[8][8];
    #pragma unroll
    for (int i = 0; i < 8; i++)
        #pragma unroll
        for (int j = 0; j < 8; j++) acc[i][j] = 0.f;

    int aRow = tid >> 1;          // 0..127
    int aCol = (tid & 1) * 4;     // 0 or 4
    int bRow = tid >> 5;          // 0..7
    int bCol = (tid & 31) * 4;    // 0..124

    for (int k0 = 0; k0 < K; k0 += 8) {
        float4 a4 = *reinterpret_cast<const float4*>(&A[(size_t)(row0 + aRow)*K + k0 + aCol]);
        As[aCol+0][aRow] = a4.x; As[aCol+1][aRow] = a4.y;
        As[aCol+2][aRow] = a4.z; As[aCol+3][aRow] = a4.w;
        #pragma unroll
        for (int q = 0; q < 4; q++) {
            int cg = col0 + bCol + q;
            Bs[bRow][bCol+q] = (cg < N) ? W[(size_t)(k0 + bRow)*N + cg] : 0.f;
        }
        __syncthreads();
        #pragma unroll
        for (int kk = 0; kk < 8; kk++) {
            float a[8], bb[8];
            float4 av0 = *reinterpret_cast<float4*>(&As[kk][ty*8]);
            float4 av1 = *reinterpret_cast<float4*>(&As[kk][ty*8+4]);
            float4 bv0 = *reinterpret_cast<float4*>(&Bs[kk][tx*8]);
            float4 bv1 = *reinterpret_cast<float4*>(&Bs[kk][tx*8+4]);
            a[0]=av0.x; a[1]=av0.y; a[2]=av0.z; a[3]=av0.w;
            a[4]=av1.x; a[5]=av1.y; a[6]=av1.z; a[7]=av1.w;
            bb[0]=bv0.x; bb[1]=bv0.y; bb[2]=bv0.z; bb[3]=bv0.w;
            bb[4]=bv1.x; bb[5]=bv1.y; bb[6]=bv1.z; bb[7]=bv1.w;
            #pragma unroll
            for (int i = 0; i < 8; i++)
                #pragma unroll
                for (int j = 0; j < 8; j++)
                    acc[i][j] += a[i]*bb[j];
        }
        __syncthreads();
    }
    #pragma unroll
    for (int i = 0; i < 8; i++) {
        int m = row0 + ty*8 + i;
        #pragma unroll
        for (int j = 0; j < 8; j++) {
            int n = col0 + tx*8 + j;
            if (n >= N) continue;
            float v = acc[i][j];
            if (MODE == 0) {
                float al = gamma[n]*BNS;
                v = fmaxf(v*al + (bias[n]*al + beta[n]), 0.f);
                out[(size_t)m*N + n] = v;
            } else if (MODE == 1) {
                out[(size_t)m*N + n] = resIn[(size_t)m*N + n] + v + bias[n];
            } else {
                float al = gamma[n]*BNS;
                v = fmaxf(v*al + (bias[n]*al + beta[n]), 0.f);
                atomicMax((unsigned int*)&out[(size_t)(m >> 11)*N + n], __float_as_uint(v));
            }
        }
    }
}

__global__ void init_out(float* out) {
    int i = blockIdx.x*256 + threadIdx.x;
    if (i < B*170) out[i] = 0.f;
}

// ---------------- launch ----------------
extern "C" void kernel_launch(void* const* d_in, const int* in_sizes, int n_in,
                              void* d_out, int out_size)
{
    const float* points = (const float*)d_in[0];
    const float* noise  = (const float*)d_in[1];
    const float* tw   = (const float*)d_in[2];
    const float* tb   = (const float*)d_in[3];
    const float* tg1  = (const float*)d_in[4];
    const float* tbt1 = (const float*)d_in[5];
    const float* td1w = (const float*)d_in[6];
    const float* td1b = (const float*)d_in[7];
    const float* tg2  = (const float*)d_in[8];
    const float* tbt2 = (const float*)d_in[9];
    const float* td2w = (const float*)d_in[10];
    const float* td2b = (const float*)d_in[11];
    const float* c1w  = (const float*)d_in[12];
    const float* c1b  = (const float*)d_in[13];
    const float* g1   = (const float*)d_in[14];
    const float* be1  = (const float*)d_in[15];
    const float* rw   = (const float*)d_in[16];
    const float* rb   = (const float*)d_in[17];
    const float* b1w  = (const float*)d_in[18];
    const float* b1b  = (const float*)d_in[19];
    const float* b1g  = (const float*)d_in[20];
    const float* b1be = (const float*)d_in[21];
    const float* b2w  = (const float*)d_in[22];
    const float* b2b  = (const float*)d_in[23];
    const float* b2g  = (const float*)d_in[24];
    const float* b2be = (const float*)d_in[25];
    const float* b3w  = (const float*)d_in[26];
    const float* b3b  = (const float*)d_in[27];
    const float* b3g  = (const float*)d_in[28];
    const float* b3be = (const float*)d_in[29];
    float* out = (float*)d_out;

    float *xmax, *Tm, *pts, *feats, *f0, *f1;
    cudaGetSymbolAddress((void**)&xmax,  g_xmax);
    cudaGetSymbolAddress((void**)&Tm,    g_T);
    cudaGetSymbolAddress((void**)&pts,   g_pts);
    cudaGetSymbolAddress((void**)&feats, g_feats);
    cudaGetSymbolAddress((void**)&f0,    g_f0);
    cudaGetSymbolAddress((void**)&f1,    g_f1);

    init_out<<<(B*170 + 255)/256, 256>>>(out);

    // T-Net
    tnet_conv_max<<<B, TU>>>(points, tw, tb, tg1, tbt1, xmax);
    tnet_dense<<<B, TU>>>(xmax, td1w, td1b, tg2, tbt2, td2w, td2b, Tm);
    transform_pts<<<(M_TOT + 255)/256, 256>>>(points, Tm, pts);

    // ball query + gather
    const int SMEM_SEL = (NP*3 + NP + NP)*4 + NP*8 + KNN*4;  // 57600 B
    cudaFuncSetAttribute(ballquery_kernel, cudaFuncAttributeMaxDynamicSharedMemorySize, SMEM_SEL);
    ballquery_kernel<<<M_TOT, 256, SMEM_SEL>>>(noise, feats);

    // MLP stack
    gemm_fused<0><<<dim3(4,128), 256>>>(feats, c1w, c1b, g1, be1, nullptr, f0, M_TOT, FEAT, 512);
    gemm_fused<1><<<dim3(4,128), 256>>>(f0, rw, rb, nullptr, nullptr, f0, f1, M_TOT, 512, 512);
    gemm_fused<0><<<dim3(4,128), 256>>>(f1, b1w, b1b, b1g, b1be, nullptr, f0, M_TOT, 512, 512);
    gemm_fused<0><<<dim3(2,128), 256>>>(f0, b2w, b2b, b2g, b2be, nullptr, f1, M_TOT, 512, 256);
    gemm_fused<2><<<dim3(2,128), 256>>>(f1, b3w, b3b, b3g, b3be, nullptr, out, M_TOT, 256, 170);
}

// round 2
// speedup vs baseline: 1.0616x; 1.0616x over previous
#include <cuda_runtime.h>
#include <math.h>
#include <stdint.h>

#define BNS 0.9995003746f  // float32(1/sqrt(1+1e-3))

#define B  8
#define NP 2048
#define KNN 64
#define TU 256
#define FEAT 576   // 3*K*3
#define M_TOT (B*NP)   // 16384

// ---------------- scratch (device globals; no allocation allowed) ----------------
__device__ float g_xmax[B*TU];
__device__ float g_T[B*9];
__device__ float g_pts[B*NP*3];
__device__ float g_feats[M_TOT*FEAT];     // 37.7 MB
__device__ float g_f0[M_TOT*512];         // 33.5 MB
__device__ float g_f1[M_TOT*512];         // 33.5 MB

// ---------------- T-Net stage 1: 1x1 conv + BN + ReLU + global max over N ----------------
__global__ void tnet_conv_max(const float* __restrict__ points,
                              const float* __restrict__ tw, const float* __restrict__ tb,
                              const float* __restrict__ tg1, const float* __restrict__ tbt1,
                              float* __restrict__ xmax)
{
    __shared__ float P[NP*3];
    int b = blockIdx.x, u = threadIdx.x;
    const float* pb = points + b*NP*3;
    for (int t = u; t < NP*3; t += TU) P[t] = pb[t];
    __syncthreads();
    float w0 = tw[u], w1 = tw[TU+u], w2 = tw[2*TU+u], bb = tb[u];
    float al = tg1[u]*BNS, bt = tbt1[u];
    float m = 0.f;
    for (int n = 0; n < NP; n++) {
        float z = P[n*3]*w0 + P[n*3+1]*w1 + P[n*3+2]*w2 + bb;
        z = fmaxf(z*al + bt, 0.f);
        m = fmaxf(m, z);
    }
    xmax[b*TU+u] = m;
}

// ---------------- T-Net stage 2: dense->BN->ReLU, then 9-wide dense -> T matrix ----------------
__global__ void tnet_dense(const float* __restrict__ xmax,
                           const float* __restrict__ td1w, const float* __restrict__ td1b,
                           const float* __restrict__ tg2, const float* __restrict__ tbt2,
                           const float* __restrict__ td2w, const float* __restrict__ td2b,
                           float* __restrict__ Tout)
{
    __shared__ float xm[TU];
    __shared__ float x2[TU];
    int b = blockIdx.x, u = threadIdx.x;
    xm[u] = xmax[b*TU+u];
    __syncthreads();
    float s = td1b[u];
    for (int v = 0; v < TU; v++) s += xm[v]*td1w[v*TU+u];
    s = fmaxf(s*(tg2[u]*BNS) + tbt2[u], 0.f);
    x2[u] = s;
    __syncthreads();
    if (u < 9) {
        float t = td2b[u];
        for (int v = 0; v < TU; v++) t += x2[v]*td2w[v*9+u];
        Tout[b*9+u] = t;
    }
}

// ---------------- apply T: pts = points @ T ----------------
__global__ void transform_pts(const float* __restrict__ points,
                              const float* __restrict__ Tm, float* __restrict__ pts)
{
    int i = blockIdx.x*256 + threadIdx.x;
    if (i >= M_TOT) return;
    int b = i >> 11;
    const float* T = Tm + b*9;
    float x = points[i*3], y = points[i*3+1], z = points[i*3+2];
    pts[i*3+0] = x*T[0] + y*T[3] + z*T[6];
    pts[i*3+1] = x*T[1] + y*T[4] + z*T[7];
    pts[i*3+2] = x*T[2] + y*T[5] + z*T[8];
}

// ---------------- ball query + stable top-K + gather -> feats ----------------
__global__ void ballquery_kernel(const float* __restrict__ noise, float* __restrict__ feats)
{
    extern __shared__ char smraw[];
    float* ptsS = (float*)smraw;                        // 6144 floats
    float* noiS = ptsS + NP*3;                          // 2048
    float* dS   = noiS + NP;                            // 2048
    unsigned long long* buf = (unsigned long long*)(dS + NP); // 2048 u64
    int* idxS = (int*)(buf + NP);                       // 64
    __shared__ int cnt;

    int b = blockIdx.x >> 11;
    int i = blockIdx.x & (NP-1);
    int tid = threadIdx.x;

    const float* pg = g_pts + b*NP*3;
    for (int t = tid; t < NP*3; t += 256) ptsS[t] = pg[t];
    const float* ng = noise + ((size_t)b*NP + i)*NP;
    for (int t = tid; t < NP; t += 256) noiS[t] = ng[t];
    __syncthreads();

    float px = ptsS[i*3], py = ptsS[i*3+1], pz = ptsS[i*3+2];
    for (int j = tid; j < NP; j += 256) {
        float dx = px - ptsS[j*3], dy = py - ptsS[j*3+1], dz = pz - ptsS[j*3+2];
        dS[j] = sqrtf(dx*dx + dy*dy + dz*dz);
    }
    __syncthreads();

    const float radii[3] = {0.1f, 0.3f, 0.7f};
    float* fout = feats + ((size_t)blockIdx.x)*FEAT;

    for (int r = 0; r < 3; r++) {
        float rad = radii[r];
        if (tid == 0) cnt = 0;
        __syncthreads();
        for (int j = tid; j < NP; j += 256) {
            float sc = noiS[j];
            if (dS[j] <= rad && sc > 0.f) {
                int p = atomicAdd(&cnt, 1);
                buf[p] = ((unsigned long long)__float_as_uint(sc) << 32)
                       | (unsigned)(0xFFFFFFFFu - (unsigned)j);
            }
        }
        __syncthreads();
        int c = cnt;
        int S = 64; while (S < c) S <<= 1;
        for (int t = c + tid; t < S; t += 256) buf[t] = 0ULL;
        __syncthreads();
        // bitonic sort, descending (keys unique -> deterministic result)
        for (int k = 2; k <= S; k <<= 1) {
            for (int jj = k >> 1; jj > 0; jj >>= 1) {
                for (int t = tid; t < S; t += 256) {
                    int ixj = t ^ jj;
                    if (ixj > t) {
                        bool desc = ((t & k) == 0);
                        unsigned long long x = buf[t], y = buf[ixj];
                        if ((x < y) == desc) { buf[t] = y; buf[ixj] = x; }
                    }
                }
                __syncthreads();
            }
        }
        int cc = c < KNN ? c : KNN;
        if (tid < KNN && tid < cc)
            idxS[tid] = (int)(0xFFFFFFFFu - (unsigned)(buf[tid] & 0xFFFFFFFFu));
        __syncthreads();
        if (tid == 0 && c < KNN) {
            int w = c;
            for (int j = 0; j < NP && w < KNN; j++)
                if (!(dS[j] <= rad && noiS[j] > 0.f)) idxS[w++] = j;
        }
        __syncthreads();
        for (int t = tid; t < KNN*3; t += 256) {
            int k = t / 3, co = t % 3;
            fout[k*9 + r*3 + co] = ptsS[idxS[k]*3 + co];
        }
        __syncthreads();
    }
}

// ---------------- double-buffered fused SGEMM: C = epilogue(A[M,K] @ W[K,N]) ----------------
// MODE 0: relu(bn(acc + bias, gamma, beta))          -> out[m*N+n]
// MODE 1: resIn[m*N+n] + acc + bias[n]               -> out[m*N+n]
// MODE 2: relu(bn(...)) then atomicMax into out[(m>>11)*N + n]  (max over points)
template<int MODE>
__global__ __launch_bounds__(256, 2)
void gemm_fused(const float* __restrict__ A, const float* __restrict__ W,
                const float* __restrict__ bias, const float* __restrict__ gamma,
                const float* __restrict__ beta, const float* __restrict__ resIn,
                float* __restrict__ out, int M, int K, int N)
{
    __shared__ float As[2][8][128];
    __shared__ float Bs[2][8][132];
    int tid = threadIdx.x;
    int row0 = blockIdx.y * 128, col0 = blockIdx.x * 128;
    int tx = tid & 15, ty = tid >> 4;
    float acc[8][8];
    #pragma unroll
    for (int i = 0; i < 8; i++)
        #pragma unroll
        for (int j = 0; j < 8; j++) acc[i][j] = 0.f;

    int aRow = tid >> 1;          // 0..127
    int aCol = (tid & 1) * 4;     // 0 or 4
    int bRow = tid >> 5;          // 0..7
    int bCol = (tid & 31) * 4;    // 0..124

    const float* Ap = A + (size_t)(row0 + aRow)*K + aCol;
    const float* Wp = W + (size_t)bRow*N;

    // ---- preload tile 0 ----
    {
        float4 a4 = *reinterpret_cast<const float4*>(Ap);
        As[0][aCol+0][aRow] = a4.x; As[0][aCol+1][aRow] = a4.y;
        As[0][aCol+2][aRow] = a4.z; As[0][aCol+3][aRow] = a4.w;
        #pragma unroll
        for (int q = 0; q < 4; q++) {
            int cg = col0 + bCol + q;
            Bs[0][bRow][bCol+q] = (cg < N) ? Wp[cg] : 0.f;
        }
    }
    __syncthreads();

    int buf = 0;
    for (int k0 = 0; k0 < K; k0 += 8) {
        bool more = (k0 + 8) < K;
        float4 a4n;
        float b4n[4];
        if (more) {
            a4n = *reinterpret_cast<const float4*>(Ap + k0 + 8);
            const float* Wn = Wp + (size_t)(k0 + 8)*N;
            #pragma unroll
            for (int q = 0; q < 4; q++) {
                int cg = col0 + bCol + q;
                b4n[q] = (cg < N) ? Wn[cg] : 0.f;
            }
        }
        #pragma unroll
        for (int kk = 0; kk < 8; kk++) {
            float a[8], bb[8];
            float4 av0 = *reinterpret_cast<float4*>(&As[buf][kk][ty*8]);
            float4 av1 = *reinterpret_cast<float4*>(&As[buf][kk][ty*8+4]);
            float4 bv0 = *reinterpret_cast<float4*>(&Bs[buf][kk][tx*8]);
            float4 bv1 = *reinterpret_cast<float4*>(&Bs[buf][kk][tx*8+4]);
            a[0]=av0.x; a[1]=av0.y; a[2]=av0.z; a[3]=av0.w;
            a[4]=av1.x; a[5]=av1.y; a[6]=av1.z; a[7]=av1.w;
            bb[0]=bv0.x; bb[1]=bv0.y; bb[2]=bv0.z; bb[3]=bv0.w;
            bb[4]=bv1.x; bb[5]=bv1.y; bb[6]=bv1.z; bb[7]=bv1.w;
            #pragma unroll
            for (int i = 0; i < 8; i++)
                #pragma unroll
                for (int j = 0; j < 8; j++)
                    acc[i][j] += a[i]*bb[j];
        }
        if (more) {
            int nb = buf ^ 1;
            As[nb][aCol+0][aRow] = a4n.x; As[nb][aCol+1][aRow] = a4n.y;
            As[nb][aCol+2][aRow] = a4n.z; As[nb][aCol+3][aRow] = a4n.w;
            #pragma unroll
            for (int q = 0; q < 4; q++) Bs[nb][bRow][bCol+q] = b4n[q];
            __syncthreads();
            buf = nb;
        }
    }

    #pragma unroll
    for (int i = 0; i < 8; i++) {
        int m = row0 + ty*8 + i;
        #pragma unroll
        for (int j = 0; j < 8; j++) {
            int n = col0 + tx*8 + j;
            if (n >= N) continue;
            float v = acc[i][j];
            if (MODE == 0) {
                float al = gamma[n]*BNS;
                v = fmaxf(v*al + (bias[n]*al + beta[n]), 0.f);
                out[(size_t)m*N + n] = v;
            } else if (MODE == 1) {
                out[(size_t)m*N + n] = resIn[(size_t)m*N + n] + v + bias[n];
            } else {
                float al = gamma[n]*BNS;
                v = fmaxf(v*al + (bias[n]*al + beta[n]), 0.f);
                atomicMax((unsigned int*)&out[(size_t)(m >> 11)*N + n], __float_as_uint(v));
            }
        }
    }
}

__global__ void init_out(float* out) {
    int i = blockIdx.x*256 + threadIdx.x;
    if (i < B*170) out[i] = 0.f;
}

// ---------------- launch ----------------
extern "C" void kernel_launch(void* const* d_in, const int* in_sizes, int n_in,
                              void* d_out, int out_size)
{
    const float* points = (const float*)d_in[0];
    const float* noise  = (const float*)d_in[1];
    const float* tw   = (const float*)d_in[2];
    const float* tb   = (const float*)d_in[3];
    const float* tg1  = (const float*)d_in[4];
    const float* tbt1 = (const float*)d_in[5];
    const float* td1w = (const float*)d_in[6];
    const float* td1b = (const float*)d_in[7];
    const float* tg2  = (const float*)d_in[8];
    const float* tbt2 = (const float*)d_in[9];
    const float* td2w = (const float*)d_in[10];
    const float* td2b = (const float*)d_in[11];
    const float* c1w  = (const float*)d_in[12];
    const float* c1b  = (const float*)d_in[13];
    const float* g1   = (const float*)d_in[14];
    const float* be1  = (const float*)d_in[15];
    const float* rw   = (const float*)d_in[16];
    const float* rb   = (const float*)d_in[17];
    const float* b1w  = (const float*)d_in[18];
    const float* b1b  = (const float*)d_in[19];
    const float* b1g  = (const float*)d_in[20];
    const float* b1be = (const float*)d_in[21];
    const float* b2w  = (const float*)d_in[22];
    const float* b2b  = (const float*)d_in[23];
    const float* b2g  = (const float*)d_in[24];
    const float* b2be = (const float*)d_in[25];
    const float* b3w  = (const float*)d_in[26];
    const float* b3b  = (const float*)d_in[27];
    const float* b3g  = (const float*)d_in[28];
    const float* b3be = (const float*)d_in[29];
    float* out = (float*)d_out;

    float *xmax, *Tm, *pts, *feats, *f0, *f1;
    cudaGetSymbolAddress((void**)&xmax,  g_xmax);
    cudaGetSymbolAddress((void**)&Tm,    g_T);
    cudaGetSymbolAddress((void**)&pts,   g_pts);
    cudaGetSymbolAddress((void**)&feats, g_feats);
    cudaGetSymbolAddress((void**)&f0,    g_f0);
    cudaGetSymbolAddress((void**)&f1,    g_f1);

    init_out<<<(B*170 + 255)/256, 256>>>(out);

    // T-Net
    tnet_conv_max<<<B, TU>>>(points, tw, tb, tg1, tbt1, xmax);
    tnet_dense<<<B, TU>>>(xmax, td1w, td1b, tg2, tbt2, td2w, td2b, Tm);
    transform_pts<<<(M_TOT + 255)/256, 256>>>(points, Tm, pts);

    // ball query + gather
    const int SMEM_SEL = (NP*3 + NP + NP)*4 + NP*8 + KNN*4;  // 57600 B
    cudaFuncSetAttribute(ballquery_kernel, cudaFuncAttributeMaxDynamicSharedMemorySize, SMEM_SEL);
    ballquery_kernel<<<M_TOT, 256, SMEM_SEL>>>(noise, feats);

    // MLP stack
    gemm_fused<0><<<dim3(4,128), 256>>>(feats, c1w, c1b, g1, be1, nullptr, f0, M_TOT, FEAT, 512);
    gemm_fused<1><<<dim3(4,128), 256>>>(f0, rw, rb, nullptr, nullptr, f0, f1, M_TOT, 512, 512);
    gemm_fused<0><<<dim3(4,128), 256>>>(f1, b1w, b1b, b1g, b1be, nullptr, f0, M_TOT, 512, 512);
    gemm_fused<0><<<dim3(2,128), 256>>>(f0, b2w, b2b, b2g, b2be, nullptr, f1, M_TOT, 512, 256);
    gemm_fused<2><<<dim3(2,128), 256>>>(f1, b3w, b3b, b3g, b3be, nullptr, out, M_TOT, 256, 170);
}